// round 4
// baseline (speedup 1.0000x reference)
#include <cuda_runtime.h>
#include <cstdint>

// MetaDynamics: out[p] = sum_h hgt[h] * exp(-0.5 * sum_d (cen[h,d]-col[p,d])^2 / wdt[h,d]^2)
// H=16384, P=4096, D=8.
//
// R3: main kernel was smem-crossbar-bound (8 LDS.128/warp-hill, 512B wavefront each
//     => ~64us smem vs ~36us FMA floor). Amortize: 8 points/thread (4 packed f32x2
//     pairs), 128-thread blocks -> warp-hill visits halve, smem bound ~32us ~ FMA
//     bound ~36us. CHUNK_H=128 halves partial buffer to 2MB; float4 reduce.
//
// Math: iv*(cen-col)^2 = iv*cen^2 + b*col + c*col^2 with b=-2*iv*cen, c=iv,
//       iv = -0.5*log2e/wdt^2; A = sum_d iv*cen_d^2 + log2(hgt); out += 2^(A+...).

#define N_HILLS   16384
#define N_POINTS  4096
#define N_CV      8

#define CHUNK_H   128                       // hills per block
#define NCHUNKS   (N_HILLS / CHUNK_H)       // 128
#define THREADS   128
#define NPAIRS    4                         // packed f32x2 pairs per thread
#define PTS_PER_THREAD (2 * NPAIRS)         // 8
#define PTS_PER_BLOCK  (THREADS * PTS_PER_THREAD)   // 1024
#define PTILES    (N_POINTS / PTS_PER_BLOCK)        // 4

typedef unsigned long long u64;

// Partial sums: [NCHUNKS][N_POINTS] = 2 MB device-global scratch.
__device__ __align__(16) float g_part[NCHUNKS * N_POINTS];

// ---- packed f32x2 helpers (sm_100+) ----
__device__ __forceinline__ u64 f2_add(u64 a, u64 b) {
    u64 d; asm("add.rn.f32x2 %0, %1, %2;" : "=l"(d) : "l"(a), "l"(b)); return d;
}
__device__ __forceinline__ u64 f2_fma(u64 a, u64 b, u64 c) {
    u64 d; asm("fma.rn.f32x2 %0, %1, %2, %3;" : "=l"(d) : "l"(a), "l"(b), "l"(c)); return d;
}
__device__ __forceinline__ float ex2f(float x) {
    float y; asm("ex2.approx.f32 %0, %1;" : "=f"(y) : "f"(x)); return y;
}
__device__ __forceinline__ float lg2f(float x) {
    float y; asm("lg2.approx.f32 %0, %1;" : "=f"(y) : "f"(x)); return y;
}
__device__ __forceinline__ u64 pack2(float lo, float hi) {
    u64 d;
    asm("mov.b64 %0, {%1, %2};" : "=l"(d) : "r"(__float_as_uint(lo)), "r"(__float_as_uint(hi)));
    return d;
}
__device__ __forceinline__ float f2_lo(u64 a) { return __uint_as_float((unsigned)(a)); }
__device__ __forceinline__ float f2_hi(u64 a) { return __uint_as_float((unsigned)(a >> 32)); }
__device__ __forceinline__ u64 dup_bits(float v) {
    u64 b = (u64)__float_as_uint(v);
    return b | (b << 32);
}

__global__ void __launch_bounds__(THREADS, 4)
metadyn_main(const float* __restrict__ col,
             const float* __restrict__ cen,
             const float* __restrict__ wdt,
             const float* __restrict__ hgt)
{
    // Per-hill coefficients, duplicated into both halves of u64 for packed math.
    __shared__ __align__(16) u64 s_b[CHUNK_H * N_CV];   // -2*iv*cen      (8 KB)
    __shared__ __align__(16) u64 s_c[CHUNK_H * N_CV];   // iv             (8 KB)
    __shared__ __align__(16) u64 s_A[CHUNK_H];          // sum iv*cen^2 + log2(hgt) (1 KB)
    __shared__ float s_ivc2[CHUNK_H * N_CV];            // staging (4 KB)

    const int   tid = threadIdx.x;
    const int   h0  = blockIdx.y * CHUNK_H;
    const float NEG_HALF_LOG2E = -0.72134752044448170f;

    // Fill: 1024 (hill,dim) pairs, 8 per thread.
    #pragma unroll
    for (int k = 0; k < CHUNK_H * N_CV / THREADS; ++k) {
        const int e = tid + k * THREADS;
        const int g = h0 * N_CV + e;
        float c  = cen[g];
        float w  = wdt[g];
        float iv = NEG_HALF_LOG2E / (w * w);
        s_b[e]    = dup_bits(-2.0f * iv * c);
        s_c[e]    = dup_bits(iv);
        s_ivc2[e] = iv * c * c;
    }
    __syncthreads();
    {   // one hill per thread (CHUNK_H == THREADS)
        float A = lg2f(hgt[h0 + tid]);
        #pragma unroll
        for (int d = 0; d < N_CV; ++d) A += s_ivc2[tid * N_CV + d];
        s_A[tid] = dup_bits(A);
    }
    __syncthreads();

    // Each thread owns 8 consecutive points as 4 packed pairs.
    const int p0 = blockIdx.x * PTS_PER_BLOCK + tid * PTS_PER_THREAD;
    u64 cp[NPAIRS][N_CV];
    #pragma unroll
    for (int j = 0; j < NPAIRS; ++j) {
        const float* a = col + (p0 + 2 * j) * N_CV;
        const float* b = col + (p0 + 2 * j + 1) * N_CV;
        float4 a0 = *(const float4*)(a);
        float4 a1 = *(const float4*)(a + 4);
        float4 b0 = *(const float4*)(b);
        float4 b1 = *(const float4*)(b + 4);
        cp[j][0] = pack2(a0.x, b0.x);
        cp[j][1] = pack2(a0.y, b0.y);
        cp[j][2] = pack2(a0.z, b0.z);
        cp[j][3] = pack2(a0.w, b0.w);
        cp[j][4] = pack2(a1.x, b1.x);
        cp[j][5] = pack2(a1.y, b1.y);
        cp[j][6] = pack2(a1.z, b1.z);
        cp[j][7] = pack2(a1.w, b1.w);
    }

    u64 out[NPAIRS] = {0ULL, 0ULL, 0ULL, 0ULL};

    #pragma unroll 2
    for (int h = 0; h < CHUNK_H; ++h) {
        const u64* bh = &s_b[h * N_CV];
        const u64* ch = &s_c[h * N_CV];
        const u64 Ah  = s_A[h];
        // Two dependency chains per packed pair.
        u64 aA[NPAIRS], aB[NPAIRS];
        #pragma unroll
        for (int j = 0; j < NPAIRS; ++j) { aA[j] = Ah; aB[j] = 0ULL; }

        #pragma unroll
        for (int dd = 0; dd < 4; ++dd) {
            ulonglong2 b2 = *(const ulonglong2*)&bh[2 * dd];
            ulonglong2 c2 = *(const ulonglong2*)&ch[2 * dd];
            #pragma unroll
            for (int j = 0; j < NPAIRS; ++j) {
                u64 t0 = f2_fma(c2.x, cp[j][2 * dd], b2.x);
                aA[j]  = f2_fma(t0, cp[j][2 * dd], aA[j]);
                u64 t1 = f2_fma(c2.y, cp[j][2 * dd + 1], b2.y);
                aB[j]  = f2_fma(t1, cp[j][2 * dd + 1], aB[j]);
            }
        }
        #pragma unroll
        for (int j = 0; j < NPAIRS; ++j) {
            u64 e = f2_add(aA[j], aB[j]);
            // 2^e already includes hgt (log2(hgt) folded into A)
            u64 E = pack2(ex2f(f2_lo(e)), ex2f(f2_hi(e)));
            out[j] = f2_add(out[j], E);
        }
    }

    float* dst = &g_part[blockIdx.y * N_POINTS + p0];
    #pragma unroll
    for (int j = 0; j < NPAIRS; j += 2) {
        float4 r;
        r.x = f2_lo(out[j]);     r.y = f2_hi(out[j]);
        r.z = f2_lo(out[j + 1]); r.w = f2_hi(out[j + 1]);
        *(float4*)(dst + 2 * j) = r;
    }
}

// Reduce: g_part is [NCHUNKS][N_POINTS] = [128][1024] float4-columns.
// 128 blocks x 256 threads; block covers 8 float4-cols (32 points).
// Thread: f4col = blk*8 + (tid&7), sums rows (tid>>3) + 32k, k=0..3.
#define RED_THREADS 256

__global__ void __launch_bounds__(RED_THREADS)
metadyn_reduce(float* __restrict__ out)
{
    __shared__ float4 s_red[32][8];
    const float4* gp4 = (const float4*)g_part;        // [NCHUNKS][1024]
    const int c  = threadIdx.x & 7;
    const int r0 = threadIdx.x >> 3;                  // 0..31
    const int c4 = blockIdx.x * 8 + c;

    float4 s = make_float4(0.f, 0.f, 0.f, 0.f);
    #pragma unroll
    for (int k = 0; k < NCHUNKS / 32; ++k) {
        float4 v = gp4[(r0 + 32 * k) * (N_POINTS / 4) + c4];
        s.x += v.x; s.y += v.y; s.z += v.z; s.w += v.w;
    }
    s_red[r0][c] = s;
    __syncthreads();

    if (threadIdx.x < 8) {
        float4 acc = s_red[0][threadIdx.x];
        #pragma unroll
        for (int r = 1; r < 32; ++r) {
            float4 v = s_red[r][threadIdx.x];
            acc.x += v.x; acc.y += v.y; acc.z += v.z; acc.w += v.w;
        }
        ((float4*)out)[blockIdx.x * 8 + threadIdx.x] = acc;
    }
}

extern "C" void kernel_launch(void* const* d_in, const int* in_sizes, int n_in,
                              void* d_out, int out_size)
{
    const float* col = (const float*)d_in[0];
    const float* cen = (const float*)d_in[1];
    const float* wdt = (const float*)d_in[2];
    const float* hgt = (const float*)d_in[3];
    float* out = (float*)d_out;

    dim3 grid(PTILES, NCHUNKS);
    metadyn_main<<<grid, THREADS>>>(col, cen, wdt, hgt);
    metadyn_reduce<<<(N_POINTS / 4) / 8, RED_THREADS>>>(out);
}

// round 6
// speedup vs baseline: 1.3713x; 1.3713x over previous
#include <cuda_runtime.h>
#include <cuda_bf16.h>
#include <cstdint>

// MetaDynamics via mma.sync bf16 tensor cores (compute_100-safe: no tcgen05).
// e[p,h] = sum_k M[h,k] * X[k,p], K = 17 (8 b*x + 8 c*x^2 + bias) padded to 32.
//   iv = -0.5*log2e/wdt^2; b = -2*iv*cen; c = iv; A = sum iv*cen^2 + log2(hgt)
//   out[p] = sum_h 2^(e[p,h])
// bf16 hi/lo split, 3 logical GEMMs (Xhi*Mhi + Xhi*Mlo + Xlo*Mhi) fused into one
// 6-mma accumulation chain per C tile. Rows: 64 bf16; cols [0,32)=hi, [32,64)=lo.
//
// Main kernel: 256 thr = 8 warps; warp owns 16 points (A frags in regs, loaded once);
// hills stream via smem chunks of 64 rows (pitch 144B -> conflict-free ldmatrix),
// double-buffered cp.async. Grid: 32 point-tiles x 8 hill-splits.

#define N_HILLS   16384
#define N_POINTS  4096
#define N_CV      8
#define ROW_BF16  64

#define SPLITS    8
#define HILLS_PER_SPLIT (N_HILLS / SPLITS)      // 2048
#define CHUNK     64
#define NCHUNKS_CTA (HILLS_PER_SPLIT / CHUNK)   // 32
#define PITCH     144                           // 128B data + 16B pad (conflict-free LDSM)
#define BUF_BYTES (CHUNK * PITCH)               // 9216

// ---- device-global scratch ----
__device__ __align__(16) __nv_bfloat16 g_X[N_POINTS * ROW_BF16];   // 512 KB
__device__ __align__(16) __nv_bfloat16 g_M[N_HILLS * ROW_BF16];    // 2 MB
__device__ __align__(16) float g_part[SPLITS * N_POINTS];          // 128 KB

// ---- helpers ----
__device__ __forceinline__ uint32_t smem_u32(const void* p) {
    uint32_t a;
    asm("{ .reg .u64 t; cvta.to.shared.u64 t, %1; cvt.u32.u64 %0, t; }" : "=r"(a) : "l"(p));
    return a;
}
__device__ __forceinline__ float ex2f(float x) {
    float y; asm("ex2.approx.f32 %0, %1;" : "=f"(y) : "f"(x)); return y;
}
__device__ __forceinline__ void cp16(uint32_t dst, const void* src) {
    asm volatile("cp.async.cg.shared.global [%0], [%1], 16;" :: "r"(dst), "l"(src));
}
__device__ __forceinline__ void cp_commit() { asm volatile("cp.async.commit_group;" ::: "memory"); }
__device__ __forceinline__ void cp_wait1()  { asm volatile("cp.async.wait_group 1;" ::: "memory"); }
__device__ __forceinline__ void cp_wait0()  { asm volatile("cp.async.wait_group 0;" ::: "memory"); }

#define LDSM4(r, addr) \
    asm volatile("ldmatrix.sync.aligned.m8n8.x4.shared.b16 {%0,%1,%2,%3}, [%4];" \
        : "=r"((r)[0]), "=r"((r)[1]), "=r"((r)[2]), "=r"((r)[3]) : "r"(addr))

__device__ __forceinline__ void mma_acc(float c[4], const uint32_t a[4],
                                        uint32_t b0, uint32_t b1) {
    asm volatile(
        "mma.sync.aligned.m16n8k16.row.col.f32.bf16.bf16.f32 "
        "{%0,%1,%2,%3}, {%4,%5,%6,%7}, {%8,%9}, {%0,%1,%2,%3};"
        : "+f"(c[0]), "+f"(c[1]), "+f"(c[2]), "+f"(c[3])
        : "r"(a[0]), "r"(a[1]), "r"(a[2]), "r"(a[3]), "r"(b0), "r"(b1));
}

__device__ __forceinline__ void bf16_split(float v, __nv_bfloat16& hi, __nv_bfloat16& lo) {
    hi = __float2bfloat16_rn(v);
    lo = __float2bfloat16_rn(v - __bfloat162float(hi));
}

// ===== precompute: point matrix X [4096][64] =====
__global__ void __launch_bounds__(128)
pre_points(const float* __restrict__ col)
{
    const int p = blockIdx.x * 128 + threadIdx.x;
    const float* c = col + p * N_CV;
    __nv_bfloat16 row[ROW_BF16];
    #pragma unroll
    for (int i = 0; i < ROW_BF16; ++i) row[i] = __float2bfloat16_rn(0.0f);
    #pragma unroll
    for (int d = 0; d < N_CV; ++d) {
        float x = c[d];
        __nv_bfloat16 hi, lo;
        bf16_split(x, hi, lo);
        row[d] = hi; row[32 + d] = lo;
        float qv = x * x;
        bf16_split(qv, hi, lo);
        row[8 + d] = hi; row[40 + d] = lo;
    }
    row[16] = __float2bfloat16_rn(1.0f);   // bias (exact; lo = 0)
    __nv_bfloat16* dst = g_X + p * ROW_BF16;
    #pragma unroll
    for (int i = 0; i < ROW_BF16; ++i) dst[i] = row[i];
}

// ===== precompute: hill coefficient matrix M [16384][64] =====
__global__ void __launch_bounds__(128)
pre_hills(const float* __restrict__ cen,
          const float* __restrict__ wdt,
          const float* __restrict__ hgt)
{
    const int h = blockIdx.x * 128 + threadIdx.x;
    const float NEG_HALF_LOG2E = -0.72134752044448170f;
    __nv_bfloat16 row[ROW_BF16];
    #pragma unroll
    for (int i = 0; i < ROW_BF16; ++i) row[i] = __float2bfloat16_rn(0.0f);
    float A = log2f(hgt[h]);
    #pragma unroll
    for (int d = 0; d < N_CV; ++d) {
        float c  = cen[h * N_CV + d];
        float w  = wdt[h * N_CV + d];
        float iv = NEG_HALF_LOG2E / (w * w);
        float b  = -2.0f * iv * c;
        A = fmaf(iv * c, c, A);
        __nv_bfloat16 hi, lo;
        bf16_split(b, hi, lo);  row[d] = hi;     row[32 + d] = lo;
        bf16_split(iv, hi, lo); row[8 + d] = hi; row[40 + d] = lo;
    }
    __nv_bfloat16 hi, lo;
    bf16_split(A, hi, lo);
    row[16] = hi; row[48] = lo;     // pairs with X bias (hi=1, lo=0)
    __nv_bfloat16* dst = g_M + h * ROW_BF16;
    #pragma unroll
    for (int i = 0; i < ROW_BF16; ++i) dst[i] = row[i];
}

// ===== main tensor-core kernel =====
__device__ __forceinline__ void copy_chunk(uint32_t bufaddr, const char* src_base, int tid)
{
    // 64 rows x 128B, padded to PITCH in smem. 512 x 16B chunks, 2 per thread.
    #pragma unroll
    for (int k = 0; k < 2; ++k) {
        const int idx = tid + k * 256;
        const int row = idx >> 3;
        const int c   = idx & 7;
        cp16(bufaddr + row * PITCH + c * 16, src_base + row * 128 + c * 16);
    }
}

__global__ void __launch_bounds__(256, 2)
metadyn_mma()
{
    __shared__ __align__(16) char sbuf[2 * BUF_BYTES];

    const int tid  = threadIdx.x;
    const int lane = tid & 31;
    const int warp = tid >> 5;
    const int q    = lane & 3;          // thread-in-group
    const int g    = lane >> 2;         // group id (row / n within 8)
    const int split = blockIdx.y;
    const int p0w  = blockIdx.x * 128 + warp * 16;   // warp's first point
    const int hbase = split * HILLS_PER_SPLIT;

    // ---- A fragments: 4 sets (hi k0-15, hi k16-31, lo k0-15, lo k16-31) ----
    // m16n8k16 A layout: a0=(row g, k 2q..2q+1), a1=(row g+8, same), a2=(row g, +8), a3=(row g+8, +8)
    uint32_t A[4][4];
    {
        const uint32_t* X32 = (const uint32_t*)g_X;   // 32 u32 per row
        const int rlo = p0w + g, rhi = rlo + 8;
        #pragma unroll
        for (int s = 0; s < 4; ++s) {
            A[s][0] = X32[rlo * 32 + s * 8 + q];
            A[s][1] = X32[rhi * 32 + s * 8 + q];
            A[s][2] = X32[rlo * 32 + s * 8 + 4 + q];
            A[s][3] = X32[rhi * 32 + s * 8 + 4 + q];
        }
    }

    const uint32_t sb = smem_u32(sbuf);
    // ldmatrix x4 lane address: lanes 0-7 mat0 rows, 8-15 mat1(+16B), 16-23 mat2(rows+8), 24-31 mat3
    const uint32_t lanebase = (uint32_t)(((lane & 7) | ((lane >> 4) << 3)) * PITCH
                                         + ((lane >> 3) & 1) * 16);

    // Prefetch chunk 0
    copy_chunk(sb, (const char*)g_M + (size_t)hbase * 128, tid);
    cp_commit();

    float acc0 = 0.f, acc1 = 0.f;

    for (int ch = 0; ch < NCHUNKS_CTA; ++ch) {
        const uint32_t buf = sb + (uint32_t)(ch & 1) * BUF_BYTES;
        if (ch + 1 < NCHUNKS_CTA) {
            copy_chunk(sb + (uint32_t)((ch + 1) & 1) * BUF_BYTES,
                       (const char*)g_M + (size_t)(hbase + (ch + 1) * CHUNK) * 128, tid);
            cp_commit();
            cp_wait1();
        } else {
            cp_wait0();
        }
        __syncthreads();   // chunk ch visible to all warps

        #pragma unroll
        for (int st = 0; st < 4; ++st) {       // 16 hills per step
            const uint32_t base = buf + (uint32_t)st * (16 * PITCH) + lanebase;
            uint32_t bh0[4], bh1[4], bl0[4], bl1[4];
            LDSM4(bh0, base + 0);    // M hi, k0-15  : {n0 frag, n1 frag}
            LDSM4(bh1, base + 32);   // M hi, k16-31
            LDSM4(bl0, base + 64);   // M lo, k0-15
            LDSM4(bl1, base + 96);   // M lo, k16-31

            float C0[4] = {0.f, 0.f, 0.f, 0.f};
            float C1[4] = {0.f, 0.f, 0.f, 0.f};
            // n-group 0: 6-mma chain = Xhi*Mhi(2) + Xhi*Mlo(2) + Xlo*Mhi(2)
            mma_acc(C0, A[0], bh0[0], bh0[1]);
            mma_acc(C0, A[1], bh1[0], bh1[1]);
            mma_acc(C0, A[0], bl0[0], bl0[1]);
            mma_acc(C0, A[1], bl1[0], bl1[1]);
            mma_acc(C0, A[2], bh0[0], bh0[1]);
            mma_acc(C0, A[3], bh1[0], bh1[1]);
            // n-group 1
            mma_acc(C1, A[0], bh0[2], bh0[3]);
            mma_acc(C1, A[1], bh1[2], bh1[3]);
            mma_acc(C1, A[0], bl0[2], bl0[3]);
            mma_acc(C1, A[1], bl1[2], bl1[3]);
            mma_acc(C1, A[2], bh0[2], bh0[3]);
            mma_acc(C1, A[3], bh1[2], bh1[3]);

            // epilogue: out += 2^e ; c0,c1 -> point row g ; c2,c3 -> row g+8
            acc0 += ex2f(C0[0]) + ex2f(C0[1]) + ex2f(C1[0]) + ex2f(C1[1]);
            acc1 += ex2f(C0[2]) + ex2f(C0[3]) + ex2f(C1[2]) + ex2f(C1[3]);
        }
        __syncthreads();   // all warps done with chunk ch before its buffer is refilled
    }

    // quad reduce (lanes sharing g hold disjoint hill columns)
    acc0 += __shfl_xor_sync(0xFFFFFFFFu, acc0, 1);
    acc0 += __shfl_xor_sync(0xFFFFFFFFu, acc0, 2);
    acc1 += __shfl_xor_sync(0xFFFFFFFFu, acc1, 1);
    acc1 += __shfl_xor_sync(0xFFFFFFFFu, acc1, 2);
    if (q == 0) {
        g_part[split * N_POINTS + p0w + g]     = acc0;
        g_part[split * N_POINTS + p0w + g + 8] = acc1;
    }
}

// ===== final reduce over 8 splits =====
__global__ void __launch_bounds__(256)
metadyn_reduce(float* __restrict__ out)
{
    const int p = blockIdx.x * 256 + threadIdx.x;
    float s = 0.f;
    #pragma unroll
    for (int k = 0; k < SPLITS; ++k) s += g_part[k * N_POINTS + p];
    out[p] = s;
}

extern "C" void kernel_launch(void* const* d_in, const int* in_sizes, int n_in,
                              void* d_out, int out_size)
{
    const float* col = (const float*)d_in[0];
    const float* cen = (const float*)d_in[1];
    const float* wdt = (const float*)d_in[2];
    const float* hgt = (const float*)d_in[3];
    float* out = (float*)d_out;

    pre_points<<<N_POINTS / 128, 128>>>(col);
    pre_hills<<<N_HILLS / 128, 128>>>(cen, wdt, hgt);
    dim3 grid(N_POINTS / 128, SPLITS);
    metadyn_mma<<<grid, 256>>>();
    metadyn_reduce<<<N_POINTS / 256, 256>>>(out);
}

// round 7
// speedup vs baseline: 1.9498x; 1.4219x over previous
#include <cuda_runtime.h>
#include <cuda_bf16.h>
#include <cstdint>

// MetaDynamics via mma.sync bf16 tensor cores (compute_100-safe).
// e[p,h] = A_h + sum_{k<16} M[h,k] * X[k,p];  K=16 (8 b*x + 8 c*x^2), bias in epilogue.
//   iv = -0.5*log2e/wdt^2; b = -2*iv*cen; c = iv; A = sum iv*cen^2 + log2(hgt)
//   out[p] = sum_h 2^(e[p,h])
// bf16 hi/lo split: 3 MMAs per C tile (Xhi*Mhi + Xhi*Mlo + Xlo*Mhi), K=16 each.
// M row: 32 bf16 = 64 B: [0,8)=b hi, [8,16)=c hi, [16,24)=b lo, [24,32)=c lo.
// A_h kept fp32, added per-lane in the epilogue before ex2.
// Warp owns 16 points; A-fragments (X hi/lo) computed in-register from col (no g_X).
// Hills stream via smem chunks of 128 rows (pitch 80 B, conflict-free LDSM),
// double-buffered cp.async. Grid: 32 point-tiles x 8 hill-splits = 256 CTAs.

#define N_HILLS   16384
#define N_POINTS  4096
#define N_CV      8

#define SPLITS    8
#define HILLS_PER_SPLIT (N_HILLS / SPLITS)      // 2048
#define CHUNK     128
#define NCHUNKS_CTA (HILLS_PER_SPLIT / CHUNK)   // 16
#define PITCH     80                            // 64B data + 16B pad (conflict-free LDSM)
#define BUF_DATA  (CHUNK * PITCH)               // 10240
#define BUF_A     (CHUNK * 4)                   // 512
#define BUF_BYTES (BUF_DATA + BUF_A)            // 10752

// ---- device-global scratch ----
__device__ __align__(16) __nv_bfloat16 g_M[N_HILLS * 32];     // 1 MB
__device__ __align__(16) float g_A[N_HILLS];                  // 64 KB
__device__ __align__(16) float g_part[N_POINTS * SPLITS];     // 128 KB (transposed [p][split])

// ---- helpers ----
__device__ __forceinline__ uint32_t smem_u32(const void* p) {
    uint32_t a;
    asm("{ .reg .u64 t; cvta.to.shared.u64 t, %1; cvt.u32.u64 %0, t; }" : "=r"(a) : "l"(p));
    return a;
}
__device__ __forceinline__ float ex2f(float x) {
    float y; asm("ex2.approx.f32 %0, %1;" : "=f"(y) : "f"(x)); return y;
}
__device__ __forceinline__ void cp16(uint32_t dst, const void* src) {
    asm volatile("cp.async.cg.shared.global [%0], [%1], 16;" :: "r"(dst), "l"(src));
}
__device__ __forceinline__ void cp_commit() { asm volatile("cp.async.commit_group;" ::: "memory"); }
__device__ __forceinline__ void cp_wait1()  { asm volatile("cp.async.wait_group 1;" ::: "memory"); }
__device__ __forceinline__ void cp_wait0()  { asm volatile("cp.async.wait_group 0;" ::: "memory"); }

#define LDSM4(r, addr) \
    asm volatile("ldmatrix.sync.aligned.m8n8.x4.shared.b16 {%0,%1,%2,%3}, [%4];" \
        : "=r"((r)[0]), "=r"((r)[1]), "=r"((r)[2]), "=r"((r)[3]) : "r"(addr))

__device__ __forceinline__ void mma_acc(float c[4], const uint32_t a[4],
                                        uint32_t b0, uint32_t b1) {
    asm volatile(
        "mma.sync.aligned.m16n8k16.row.col.f32.bf16.bf16.f32 "
        "{%0,%1,%2,%3}, {%4,%5,%6,%7}, {%8,%9}, {%0,%1,%2,%3};"
        : "+f"(c[0]), "+f"(c[1]), "+f"(c[2]), "+f"(c[3])
        : "r"(a[0]), "r"(a[1]), "r"(a[2]), "r"(a[3]), "r"(b0), "r"(b1));
}

__device__ __forceinline__ void bf16_split(float v, __nv_bfloat16& hi, __nv_bfloat16& lo) {
    hi = __float2bfloat16_rn(v);
    lo = __float2bfloat16_rn(v - __bfloat162float(hi));
}
__device__ __forceinline__ uint32_t pack_bf(__nv_bfloat16 lo16, __nv_bfloat16 hi16) {
    // low 16 bits = element k (first), high 16 = element k+1
    uint32_t l = __bfloat16_as_ushort(lo16), h = __bfloat16_as_ushort(hi16);
    return l | (h << 16);
}

// ===== precompute: hill matrix M [16384][32] + bias A [16384] =====
__global__ void __launch_bounds__(128)
pre_hills(const float* __restrict__ cen,
          const float* __restrict__ wdt,
          const float* __restrict__ hgt)
{
    const int h = blockIdx.x * 128 + threadIdx.x;
    const float NEG_HALF_LOG2E = -0.72134752044448170f;
    __nv_bfloat16 row[32];
    float A = log2f(hgt[h]);
    #pragma unroll
    for (int d = 0; d < N_CV; ++d) {
        float c  = cen[h * N_CV + d];
        float w  = wdt[h * N_CV + d];
        float iv = NEG_HALF_LOG2E / (w * w);
        float b  = -2.0f * iv * c;
        A = fmaf(iv * c, c, A);
        __nv_bfloat16 hi, lo;
        bf16_split(b, hi, lo);  row[d]     = hi; row[16 + d] = lo;
        bf16_split(iv, hi, lo); row[8 + d] = hi; row[24 + d] = lo;
    }
    __nv_bfloat16* dst = g_M + h * 32;
    #pragma unroll
    for (int i = 0; i < 32; ++i) dst[i] = row[i];
    g_A[h] = A;
}

// ===== main tensor-core kernel =====
__device__ __forceinline__ void copy_chunk(uint32_t bufaddr, int hbase, int tid)
{
    // data: 128 rows x 64 B -> pitch 80 in smem; 512 x 16B, 2 per thread
    const char* src = (const char*)g_M + (size_t)hbase * 64;
    #pragma unroll
    for (int k = 0; k < 2; ++k) {
        const int idx = tid + k * 256;
        const int row = idx >> 2;
        const int c   = idx & 3;
        cp16(bufaddr + row * PITCH + c * 16, src + row * 64 + c * 16);
    }
    // bias: 128 floats = 512 B = 32 x 16B
    if (tid < 32)
        cp16(bufaddr + BUF_DATA + tid * 16, (const char*)(g_A + hbase) + tid * 16);
}

__global__ void __launch_bounds__(256, 2)
metadyn_mma(const float* __restrict__ col)
{
    __shared__ __align__(16) char sbuf[2 * BUF_BYTES];

    const int tid  = threadIdx.x;
    const int lane = tid & 31;
    const int warp = tid >> 5;
    const int q    = lane & 3;
    const int g    = lane >> 2;
    const int split = blockIdx.y;
    const int p0w  = blockIdx.x * 128 + warp * 16;
    const int hbase = split * HILLS_PER_SPLIT;

    // ---- A fragments from col, in registers: Ahi/Alo, K=16 (k0-7 = x_d, k8-15 = x_d^2)
    // frag: a0=(row g, k 2q..2q+1), a1=(row g+8, same), a2=(row g, k 8+2q..), a3=(row g+8, ..)
    uint32_t Ahi[4], Alo[4];
    {
        const int rlo = p0w + g, rhi = rlo + 8;
        float2 xa = *(const float2*)(col + rlo * N_CV + 2 * q);
        float2 xb = *(const float2*)(col + rhi * N_CV + 2 * q);
        __nv_bfloat16 h0, l0, h1, l1;
        bf16_split(xa.x, h0, l0); bf16_split(xa.y, h1, l1);
        Ahi[0] = pack_bf(h0, h1);  Alo[0] = pack_bf(l0, l1);
        bf16_split(xb.x, h0, l0); bf16_split(xb.y, h1, l1);
        Ahi[1] = pack_bf(h0, h1);  Alo[1] = pack_bf(l0, l1);
        bf16_split(xa.x * xa.x, h0, l0); bf16_split(xa.y * xa.y, h1, l1);
        Ahi[2] = pack_bf(h0, h1);  Alo[2] = pack_bf(l0, l1);
        bf16_split(xb.x * xb.x, h0, l0); bf16_split(xb.y * xb.y, h1, l1);
        Ahi[3] = pack_bf(h0, h1);  Alo[3] = pack_bf(l0, l1);
    }

    const uint32_t sb = smem_u32(sbuf);
    // ldmatrix x4: lanes 0-7 rows 0-7 @+0 (k0-7), 8-15 rows 0-7 @+16 (k8-15),
    //              16-23 rows 8-15 @+0, 24-31 rows 8-15 @+16
    const uint32_t lanebase = (uint32_t)(((lane & 7) | ((lane >> 4) << 3)) * PITCH
                                         + ((lane >> 3) & 1) * 16);

    copy_chunk(sb, hbase, tid);
    cp_commit();

    float acc0 = 0.f, acc1 = 0.f;

    for (int ch = 0; ch < NCHUNKS_CTA; ++ch) {
        const uint32_t buf = sb + (uint32_t)(ch & 1) * BUF_BYTES;
        if (ch + 1 < NCHUNKS_CTA) {
            copy_chunk(sb + (uint32_t)((ch + 1) & 1) * BUF_BYTES,
                       hbase + (ch + 1) * CHUNK, tid);
            cp_commit();
            cp_wait1();
        } else {
            cp_wait0();
        }
        __syncthreads();

        #pragma unroll
        for (int st = 0; st < CHUNK / 16; ++st) {      // 16 hills per step
            const uint32_t base = buf + (uint32_t)st * (16 * PITCH) + lanebase;
            uint32_t bh[4], bl[4];
            LDSM4(bh, base + 0);     // M hi: {n0 b0,b1, n1 b0,b1}
            LDSM4(bl, base + 32);    // M lo

            float C0[4] = {0.f, 0.f, 0.f, 0.f};
            float C1[4] = {0.f, 0.f, 0.f, 0.f};
            mma_acc(C0, Ahi, bh[0], bh[1]);
            mma_acc(C0, Ahi, bl[0], bl[1]);
            mma_acc(C0, Alo, bh[0], bh[1]);
            mma_acc(C1, Ahi, bh[2], bh[3]);
            mma_acc(C1, Ahi, bl[2], bl[3]);
            mma_acc(C1, Alo, bh[2], bh[3]);

            // bias (fp32) + exp2; C0 cols = hills st*16 + 2q,2q+1 ; C1 cols = +8
            float2 a0 = *(const float2*)(sbuf + (buf - sb) + BUF_DATA + (st * 16 + 2 * q) * 4);
            float2 a1 = *(const float2*)(sbuf + (buf - sb) + BUF_DATA + (st * 16 + 8 + 2 * q) * 4);
            acc0 += ex2f(C0[0] + a0.x) + ex2f(C0[1] + a0.y)
                  + ex2f(C1[0] + a1.x) + ex2f(C1[1] + a1.y);
            acc1 += ex2f(C0[2] + a0.x) + ex2f(C0[3] + a0.y)
                  + ex2f(C1[2] + a1.x) + ex2f(C1[3] + a1.y);
        }
        __syncthreads();
    }

    // quad reduce (lanes sharing g hold disjoint hill columns)
    acc0 += __shfl_xor_sync(0xFFFFFFFFu, acc0, 1);
    acc0 += __shfl_xor_sync(0xFFFFFFFFu, acc0, 2);
    acc1 += __shfl_xor_sync(0xFFFFFFFFu, acc1, 1);
    acc1 += __shfl_xor_sync(0xFFFFFFFFu, acc1, 2);
    if (q == 0) {
        g_part[(p0w + g) * SPLITS + split]     = acc0;   // transposed for coalesced reduce
        g_part[(p0w + g + 8) * SPLITS + split] = acc1;
    }
}

// ===== final reduce over 8 splits (coalesced: 32 B per point) =====
__global__ void __launch_bounds__(256)
metadyn_reduce(float* __restrict__ out)
{
    const int p = blockIdx.x * 256 + threadIdx.x;
    const float4* v = (const float4*)(g_part + p * SPLITS);
    float4 a = v[0], b = v[1];
    out[p] = ((a.x + a.y) + (a.z + a.w)) + ((b.x + b.y) + (b.z + b.w));
}

extern "C" void kernel_launch(void* const* d_in, const int* in_sizes, int n_in,
                              void* d_out, int out_size)
{
    const float* col = (const float*)d_in[0];
    const float* cen = (const float*)d_in[1];
    const float* wdt = (const float*)d_in[2];
    const float* hgt = (const float*)d_in[3];
    float* out = (float*)d_out;

    pre_hills<<<N_HILLS / 128, 128>>>(cen, wdt, hgt);
    dim3 grid(N_POINTS / 128, SPLITS);
    metadyn_mma<<<grid, 256>>>(col);
    metadyn_reduce<<<N_POINTS / 256, 256>>>(out);
}